// round 4
// baseline (speedup 1.0000x reference)
#include <cuda_runtime.h>
#include <cuda_bf16.h>

// Cubic B-spline activation, uniform knots t_k = k/69 (k = 0..69), p = 3.
// i = clamp(floor(x*69), 3, 65); de Boor with uniform-knot alphas:
//   r=1: alpha_j = (s + 3 - j)/3, j=3..1
//   r=2: alpha_j = (s + 3 - j)/2, j=3..2
//   r=3: alpha_3 = s
// where s = x*69 - i. d0..d3 = c[i-3..i], fetched as ONE aligned LDS.128
// from a padded shared table tab[i-3] = {c[i-3], c[i-2], c[i-1], c[i]}.

#define NTAB 63  // valid i in [3,65] -> i-3 in [0,62]

__device__ __forceinline__ float spline_eval(float xx, const float4* __restrict__ tab) {
    float u = xx * 69.0f;
    int i = (int)floorf(u);
    i = min(max(i, 3), 65);
    float s = u - (float)i;

    float4 d = tab[i - 3];
    float d0 = d.x, d1 = d.y, d2 = d.z, d3 = d.w;

    const float inv3 = (1.0f / 3.0f);
    // r = 1
    d3 = fmaf(s * inv3,            d3 - d2, d2);
    d2 = fmaf((s + 1.0f) * inv3,   d2 - d1, d1);
    d1 = fmaf((s + 2.0f) * inv3,   d1 - d0, d0);
    // r = 2
    d3 = fmaf(s * 0.5f,            d3 - d2, d2);
    d2 = fmaf((s + 1.0f) * 0.5f,   d2 - d1, d1);
    // r = 3
    d3 = fmaf(s,                   d3 - d2, d2);
    return d3;
}

__global__ void __launch_bounds__(256)
spline_act_kernel(const float* __restrict__ x,
                  const float* __restrict__ coef,
                  float* __restrict__ out,
                  int nvec) {
    __shared__ float4 tab[NTAB];
    int tid = threadIdx.x;
    if (tid < NTAB) {
        tab[tid] = make_float4(coef[tid], coef[tid + 1], coef[tid + 2], coef[tid + 3]);
    }
    __syncthreads();

    int idx = blockIdx.x * blockDim.x + tid;
    if (idx >= nvec) return;

    float4 xv = reinterpret_cast<const float4*>(x)[idx];
    float4 ov;
    ov.x = spline_eval(xv.x, tab);
    ov.y = spline_eval(xv.y, tab);
    ov.z = spline_eval(xv.z, tab);
    ov.w = spline_eval(xv.w, tab);
    reinterpret_cast<float4*>(out)[idx] = ov;
}

// Tail kernel for non-multiple-of-4 sizes (not expected here, but safe).
__global__ void spline_act_tail(const float* __restrict__ x,
                                const float* __restrict__ coef,
                                float* __restrict__ out,
                                int start, int n) {
    __shared__ float4 tab[NTAB];
    int tid = threadIdx.x;
    if (tid < NTAB) {
        tab[tid] = make_float4(coef[tid], coef[tid + 1], coef[tid + 2], coef[tid + 3]);
    }
    __syncthreads();
    int idx = start + blockIdx.x * blockDim.x + tid;
    if (idx < n) out[idx] = spline_eval(x[idx], tab);
}

extern "C" void kernel_launch(void* const* d_in, const int* in_sizes, int n_in,
                              void* d_out, int out_size) {
    // Identify inputs by size: coefficients has 67 elements, x is huge.
    const float* x    = (const float*)d_in[0];
    const float* coef = (const float*)d_in[1];
    long long n = in_sizes[0];
    if (n_in >= 2 && in_sizes[0] < in_sizes[1]) {  // defensive swap
        coef = (const float*)d_in[0];
        x    = (const float*)d_in[1];
        n    = in_sizes[1];
    }

    int nvec = (int)(n / 4);
    if (nvec > 0) {
        int threads = 256;
        int blocks = (nvec + threads - 1) / threads;
        spline_act_kernel<<<blocks, threads>>>(x, coef, (float*)d_out, nvec);
    }
    int rem = (int)(n - (long long)nvec * 4);
    if (rem > 0) {
        spline_act_tail<<<1, 256>>>(x, coef, (float*)d_out, nvec * 4, (int)n);
    }
}

// round 5
// speedup vs baseline: 1.0041x; 1.0041x over previous
#include <cuda_runtime.h>
#include <cuda_bf16.h>

// Cubic B-spline activation, uniform knots t_k = k/69, p = 3.
// i = clamp(floor(x*69), 3, 65); s = x*69 - i.
// Each interval's 4 control points c[i-3..i] are converted ONCE (at block
// start) to cubic polynomial coefficients a0..a3 via the uniform B-spline
// basis matrix; per-element eval is then a 3-FMA Horner.
//
// The poly-coef table is replicated 8x with stride-8 interleave so that
// entry (k, r) sits at slot k*8 + r  ->  bank group (slot % 8) == r.
// Each lane uses replica r = lane & 7, so every quarter-warp LDS.128 phase
// hits 8 distinct bank groups: zero conflicts, 4 wavefronts per LDS.128.

#define NTAB 63        // valid i in [3,65] -> k = i-3 in [0,62]
#define NREP 8

__device__ __forceinline__ float spline_eval(float xx, const float4* __restrict__ tab, int rep) {
    float u = xx * 69.0f;
    int i = __float2int_rd(u);
    i = min(max(i, 3), 65);
    float s = u - (float)i;

    float4 a = tab[(i - 3) * NREP + rep];
    // Horner: ((a3*s + a2)*s + a1)*s + a0
    float r = fmaf(a.w, s, a.z);
    r = fmaf(r, s, a.y);
    r = fmaf(r, s, a.x);
    return r;
}

__device__ __forceinline__ void fill_table(float4* tab, const float* __restrict__ coef, int tid, int nthreads) {
    const float inv6 = 1.0f / 6.0f;
    for (int e = tid; e < NTAB * NREP; e += nthreads) {
        int k = e >> 3;  // e / NREP
        float c0 = coef[k], c1 = coef[k + 1], c2 = coef[k + 2], c3 = coef[k + 3];
        float4 a;
        a.x = (c0 + 4.0f * c1 + c2) * inv6;          // a0
        a.y = (c2 - c0) * 0.5f;                      // a1
        a.z = (c0 - 2.0f * c1 + c2) * 0.5f;          // a2
        a.w = (c3 - 3.0f * c2 + 3.0f * c1 - c0) * inv6;  // a3
        tab[e] = a;
    }
}

__global__ void __launch_bounds__(256)
spline_act_kernel(const float* __restrict__ x,
                  const float* __restrict__ coef,
                  float* __restrict__ out,
                  int nvec) {
    __shared__ float4 tab[NTAB * NREP];
    int tid = threadIdx.x;
    fill_table(tab, coef, tid, 256);
    __syncthreads();

    int rep = tid & 7;
    int idx = blockIdx.x * blockDim.x + tid;
    if (idx >= nvec) return;

    float4 xv = reinterpret_cast<const float4*>(x)[idx];
    float4 ov;
    ov.x = spline_eval(xv.x, tab, rep);
    ov.y = spline_eval(xv.y, tab, rep);
    ov.z = spline_eval(xv.z, tab, rep);
    ov.w = spline_eval(xv.w, tab, rep);
    reinterpret_cast<float4*>(out)[idx] = ov;
}

// Tail kernel for non-multiple-of-4 sizes (not expected here, but safe).
__global__ void spline_act_tail(const float* __restrict__ x,
                                const float* __restrict__ coef,
                                float* __restrict__ out,
                                int start, int n) {
    __shared__ float4 tab[NTAB * NREP];
    int tid = threadIdx.x;
    fill_table(tab, coef, tid, 256);
    __syncthreads();
    int idx = start + blockIdx.x * blockDim.x + tid;
    if (idx < n) out[idx] = spline_eval(x[idx], tab, tid & 7);
}

extern "C" void kernel_launch(void* const* d_in, const int* in_sizes, int n_in,
                              void* d_out, int out_size) {
    const float* x    = (const float*)d_in[0];
    const float* coef = (const float*)d_in[1];
    long long n = in_sizes[0];
    if (n_in >= 2 && in_sizes[0] < in_sizes[1]) {  // defensive swap
        coef = (const float*)d_in[0];
        x    = (const float*)d_in[1];
        n    = in_sizes[1];
    }

    int nvec = (int)(n / 4);
    if (nvec > 0) {
        int threads = 256;
        int blocks = (nvec + threads - 1) / threads;
        spline_act_kernel<<<blocks, threads>>>(x, coef, (float*)d_out, nvec);
    }
    int rem = (int)(n - (long long)nvec * 4);
    if (rem > 0) {
        spline_act_tail<<<1, 256>>>(x, coef, (float*)d_out, nvec * 4, (int)n);
    }
}

// round 6
// speedup vs baseline: 1.0933x; 1.0888x over previous
#include <cuda_runtime.h>
#include <cuda_bf16.h>

// Cubic B-spline activation, uniform knots t_k = k/69, p = 3.
// i = clamp(floor(x*69), 3, 65); s = x*69 - i.
// Per-interval cubic poly coefficients a0..a3 (uniform B-spline basis matrix),
// evaluated with a 3-FMA Horner.
//
// x ~ N(0,1) while the spline domain is [0,1]: ~52% of elements clamp to
// i=3 (entry 0) and ~17% to i=65 (entry 62). Those two entries are cached in
// registers; the shared-memory gather LDS.128 is PREDICATED and only issues
// for the ~31% interior lanes, cutting L1tex wavefront traffic ~2x so the
// kernel can run at the HBM roofline instead of the L1 crossbar.

#define NTAB 63  // valid i in [3,65] -> k = i-3 in [0,62]

__device__ __forceinline__ float spline_eval(float xx,
                                             const float4* __restrict__ tab,
                                             float4 a_lo, float4 a_hi) {
    float u = xx * 69.0f;
    int i = __float2int_rd(u);
    i = min(max(i, 3), 65);
    float s = u - (float)i;

    // Branch-free select of the two register-cached boundary entries,
    // then a predicated LDS.128 for interior lanes only.
    float4 a;
    bool hi = (i >= 65);
    a.x = hi ? a_hi.x : a_lo.x;
    a.y = hi ? a_hi.y : a_lo.y;
    a.z = hi ? a_hi.z : a_lo.z;
    a.w = hi ? a_hi.w : a_lo.w;
    if (i > 3 && i < 65) {
        a = tab[i - 3];
    }

    // Horner: ((a3*s + a2)*s + a1)*s + a0
    float r = fmaf(a.w, s, a.z);
    r = fmaf(r, s, a.y);
    r = fmaf(r, s, a.x);
    return r;
}

__device__ __forceinline__ void fill_table(float4* tab, const float* __restrict__ coef,
                                           int tid, int nthreads) {
    const float inv6 = 1.0f / 6.0f;
    for (int k = tid; k < NTAB; k += nthreads) {
        float c0 = coef[k], c1 = coef[k + 1], c2 = coef[k + 2], c3 = coef[k + 3];
        float4 a;
        a.x = (c0 + 4.0f * c1 + c2) * inv6;              // a0
        a.y = (c2 - c0) * 0.5f;                          // a1
        a.z = (c0 - 2.0f * c1 + c2) * 0.5f;              // a2
        a.w = (c3 - 3.0f * c2 + 3.0f * c1 - c0) * inv6;  // a3
        tab[k] = a;
    }
}

__global__ void __launch_bounds__(256)
spline_act_kernel(const float* __restrict__ x,
                  const float* __restrict__ coef,
                  float* __restrict__ out,
                  int nvec) {
    __shared__ float4 tab[NTAB];
    int tid = threadIdx.x;
    fill_table(tab, coef, tid, 256);
    __syncthreads();

    // Broadcast loads (all lanes same address -> 1 wavefront each).
    float4 a_lo = tab[0];
    float4 a_hi = tab[NTAB - 1];

    int idx = blockIdx.x * blockDim.x + tid;
    if (idx >= nvec) return;

    float4 xv = reinterpret_cast<const float4*>(x)[idx];
    float4 ov;
    ov.x = spline_eval(xv.x, tab, a_lo, a_hi);
    ov.y = spline_eval(xv.y, tab, a_lo, a_hi);
    ov.z = spline_eval(xv.z, tab, a_lo, a_hi);
    ov.w = spline_eval(xv.w, tab, a_lo, a_hi);
    reinterpret_cast<float4*>(out)[idx] = ov;
}

// Tail kernel for non-multiple-of-4 sizes (not expected here, but safe).
__global__ void spline_act_tail(const float* __restrict__ x,
                                const float* __restrict__ coef,
                                float* __restrict__ out,
                                int start, int n) {
    __shared__ float4 tab[NTAB];
    int tid = threadIdx.x;
    fill_table(tab, coef, tid, 256);
    __syncthreads();
    float4 a_lo = tab[0];
    float4 a_hi = tab[NTAB - 1];
    int idx = start + blockIdx.x * blockDim.x + tid;
    if (idx < n) out[idx] = spline_eval(x[idx], tab, a_lo, a_hi);
}

extern "C" void kernel_launch(void* const* d_in, const int* in_sizes, int n_in,
                              void* d_out, int out_size) {
    const float* x    = (const float*)d_in[0];
    const float* coef = (const float*)d_in[1];
    long long n = in_sizes[0];
    if (n_in >= 2 && in_sizes[0] < in_sizes[1]) {  // defensive swap
        coef = (const float*)d_in[0];
        x    = (const float*)d_in[1];
        n    = in_sizes[1];
    }

    int nvec = (int)(n / 4);
    if (nvec > 0) {
        int threads = 256;
        int blocks = (nvec + threads - 1) / threads;
        spline_act_kernel<<<blocks, threads>>>(x, coef, (float*)d_out, nvec);
    }
    int rem = (int)(n - (long long)nvec * 4);
    if (rem > 0) {
        spline_act_tail<<<1, 256>>>(x, coef, (float*)d_out, nvec * 4, (int)n);
    }
}

// round 7
// speedup vs baseline: 1.1666x; 1.0670x over previous
#include <cuda_runtime.h>
#include <cuda_bf16.h>

// Cubic B-spline activation, uniform knots t_k = k/69, p = 3.
// i = clamp(floor(x*69), 3, 65); s = x*69 - i. Per-interval cubic poly
// coefficients (uniform B-spline basis), 3-FMA Horner per element.
//
// x ~ N(0,1): ~52% of elements clamp to entry 0, ~17% to entry 62. Those two
// entries live in registers; the table gather is a hand-predicated
// @p ld.shared.v4.f32 (no BSSY/BSYNC branch) issued only for ~31% of lanes.
// 4 float4 per thread with front-batched LDG.128 for MLP=4.

#define NTAB 63  // valid i in [3,65] -> k = i-3 in [0,62]
#define THREADS 256
#define VPT 4    // float4 per thread

__device__ __forceinline__ float spline_eval(float xx, unsigned tab_base,
                                             float4 a_lo, float4 a_hi) {
    float u = xx * 69.0f;
    int i = __float2int_rd(u);
    i = min(max(i, 3), 65);
    float s = u - (float)i;
    int k = i - 3;  // 0..62

    // Default: boundary entries (register-cached, covers ~69% of lanes).
    bool hi = (k == 62);
    float4 a;
    a.x = hi ? a_hi.x : a_lo.x;
    a.y = hi ? a_hi.y : a_lo.y;
    a.z = hi ? a_hi.z : a_lo.z;
    a.w = hi ? a_hi.w : a_lo.w;

    // Predicated (branch-free) shared gather for interior lanes only.
    unsigned interior = (unsigned)(k > 0 && k < 62);
    unsigned addr = tab_base + (unsigned)k * 16u;
    asm volatile(
        "{\n\t"
        ".reg .pred p;\n\t"
        "setp.ne.u32 p, %5, 0;\n\t"
        "@p ld.shared.v4.f32 {%0, %1, %2, %3}, [%4];\n\t"
        "}"
        : "+f"(a.x), "+f"(a.y), "+f"(a.z), "+f"(a.w)
        : "r"(addr), "r"(interior));

    // Horner: ((a3*s + a2)*s + a1)*s + a0
    float r = fmaf(a.w, s, a.z);
    r = fmaf(r, s, a.y);
    r = fmaf(r, s, a.x);
    return r;
}

__device__ __forceinline__ void fill_table(float4* tab, const float* __restrict__ coef,
                                           int tid, int nthreads) {
    const float inv6 = 1.0f / 6.0f;
    for (int k = tid; k < NTAB; k += nthreads) {
        float c0 = coef[k], c1 = coef[k + 1], c2 = coef[k + 2], c3 = coef[k + 3];
        float4 a;
        a.x = (c0 + 4.0f * c1 + c2) * inv6;              // a0
        a.y = (c2 - c0) * 0.5f;                          // a1
        a.z = (c0 - 2.0f * c1 + c2) * 0.5f;              // a2
        a.w = (c3 - 3.0f * c2 + 3.0f * c1 - c0) * inv6;  // a3
        tab[k] = a;
    }
}

__device__ __forceinline__ float4 eval4(float4 xv, unsigned tab_base,
                                        float4 a_lo, float4 a_hi) {
    float4 ov;
    ov.x = spline_eval(xv.x, tab_base, a_lo, a_hi);
    ov.y = spline_eval(xv.y, tab_base, a_lo, a_hi);
    ov.z = spline_eval(xv.z, tab_base, a_lo, a_hi);
    ov.w = spline_eval(xv.w, tab_base, a_lo, a_hi);
    return ov;
}

__global__ void __launch_bounds__(THREADS)
spline_act_kernel(const float4* __restrict__ x,
                  const float* __restrict__ coef,
                  float4* __restrict__ out,
                  int nvec) {
    __shared__ float4 tab[NTAB];
    int tid = threadIdx.x;
    fill_table(tab, coef, tid, THREADS);
    __syncthreads();

    unsigned tab_base = (unsigned)__cvta_generic_to_shared(tab);
    float4 a_lo = tab[0];
    float4 a_hi = tab[NTAB - 1];

    int base = blockIdx.x * (THREADS * VPT) + tid;

    if ((blockIdx.x + 1) * (THREADS * VPT) <= nvec) {
        // Fast path: full block, no bounds checks. Front-batched loads (MLP=4).
        float4 xv[VPT];
#pragma unroll
        for (int v = 0; v < VPT; v++) xv[v] = x[base + v * THREADS];
#pragma unroll
        for (int v = 0; v < VPT; v++)
            out[base + v * THREADS] = eval4(xv[v], tab_base, a_lo, a_hi);
    } else {
#pragma unroll
        for (int v = 0; v < VPT; v++) {
            int idx = base + v * THREADS;
            if (idx < nvec) out[idx] = eval4(x[idx], tab_base, a_lo, a_hi);
        }
    }
}

// Tail kernel for non-multiple-of-4 element counts (not expected here).
__global__ void spline_act_tail(const float* __restrict__ x,
                                const float* __restrict__ coef,
                                float* __restrict__ out,
                                int start, int n) {
    __shared__ float4 tab[NTAB];
    int tid = threadIdx.x;
    fill_table(tab, coef, tid, 256);
    __syncthreads();
    unsigned tab_base = (unsigned)__cvta_generic_to_shared(tab);
    float4 a_lo = tab[0];
    float4 a_hi = tab[NTAB - 1];
    int idx = start + blockIdx.x * blockDim.x + tid;
    if (idx < n) out[idx] = spline_eval(x[idx], tab_base, a_lo, a_hi);
}

extern "C" void kernel_launch(void* const* d_in, const int* in_sizes, int n_in,
                              void* d_out, int out_size) {
    const float* x    = (const float*)d_in[0];
    const float* coef = (const float*)d_in[1];
    long long n = in_sizes[0];
    if (n_in >= 2 && in_sizes[0] < in_sizes[1]) {  // defensive swap
        coef = (const float*)d_in[0];
        x    = (const float*)d_in[1];
        n    = in_sizes[1];
    }

    int nvec = (int)(n / 4);
    if (nvec > 0) {
        int per_block = THREADS * VPT;
        int blocks = (nvec + per_block - 1) / per_block;
        spline_act_kernel<<<blocks, THREADS>>>((const float4*)x, coef,
                                               (float4*)d_out, nvec);
    }
    int rem = (int)(n - (long long)nvec * 4);
    if (rem > 0) {
        spline_act_tail<<<1, 256>>>(x, coef, (float*)d_out, nvec * 4, (int)n);
    }
}